// round 14
// baseline (speedup 1.0000x reference)
#include <cuda_runtime.h>
#include <cstdint>

#define D 128
#define D4 32          // D / 4
#define N_MAX 50000
#define NPB 32         // nodes per tile in the GEMM kernel
#define LN_EPS 1e-5f
#define GEMM_BLOCKS 296   // 2 per SM (148 SMs)

// Scratch: aggregated features (agg = h + sum_{e: dst=n} h[src])
__device__ float g_agg[(size_t)N_MAX * D];
__device__ int   g_tile_ctr;      // dynamic tile scheduler for the GEMM

// ---------------------------------------------------------------------------
// Kernel 1: agg = h  (residual pre-load; scatter accumulates on top)
// Also resets the GEMM tile counter (launch order guarantees visibility).
// ---------------------------------------------------------------------------
__global__ void k_init_agg(const float4* __restrict__ h4, int n4) {
    int i = blockIdx.x * blockDim.x + threadIdx.x;
    if (i == 0) g_tile_ctr = 0;
    float4* agg4 = reinterpret_cast<float4*>(g_agg);
    if (i < n4) agg4[i] = h4[i];
}

// ---------------------------------------------------------------------------
// Kernel 2: scatter-add  agg[dst[e]] += h[src[e]]   (one warp per edge)
// One red.global.add.v4.f32 (REDG.128) per lane — at the L2 atomic op-rate
// floor (19.2M ops over 184 LTS slices).
// ---------------------------------------------------------------------------
__global__ __launch_bounds__(256)
void k_scatter_v4(const float4* __restrict__ h4,
                  const int* __restrict__ src,
                  const int* __restrict__ dst,
                  int E) {
    int warp_id = (blockIdx.x * blockDim.x + threadIdx.x) >> 5;
    int lane = threadIdx.x & 31;
    if (warp_id >= E) return;
    int s = __ldg(src + warp_id);       // warp-uniform (broadcast)
    int d = __ldg(dst + warp_id);
    float4 v = h4[(size_t)s * D4 + lane];
    float4* ap = reinterpret_cast<float4*>(g_agg) + (size_t)d * D4 + lane;
    asm volatile("red.global.add.v4.f32 [%0], {%1, %2, %3, %4};"
                 :: "l"(ap), "f"(v.x), "f"(v.y), "f"(v.z), "f"(v.w)
                 : "memory");
}

// ---------------------------------------------------------------------------
// Kernel 3: fused  y = agg @ W^T + b ; LayerNorm ; ReLU     (SPLIT-K by 2)
// 256 threads: thread (j = t&127, half = t>>7) computes K-range
// [half*64, half*64+64) of column j. Dynamic tile scheduling via global
// atomic counter (perfect load balance). Packed f32x2 reduction epilogue.
// ---------------------------------------------------------------------------
__global__ __launch_bounds__(256, 2)
void k_gemm_ln_relu(const float* __restrict__ W,
                    const float* __restrict__ bias,
                    const float* __restrict__ gamma,
                    const float* __restrict__ beta,
                    float* __restrict__ out,
                    int N) {
    __shared__ float4 xs[NPB][D4];     // input tile            (16 KB)
    __shared__ float  ys0[NPB][D];     // half-0 partials       (16 KB)
    __shared__ float  ys1[NPB][D];     // half-1 partials       (16 KB)
    __shared__ int    s_tile;

    const int t    = threadIdx.x;
    const int j    = t & 127;          // output column 0..127
    const int half = t >> 7;           // K-split half 0/1
    const int lane = t & 31;
    const int warp = t >> 5;           // 0..7

    // W row j, K-half: 16 x ulonglong2 (each .x/.y is a packed f32x2)
    ulonglong2 w[16];
    const ulonglong2* W2 = reinterpret_cast<const ulonglong2*>(W);
#pragma unroll
    for (int k = 0; k < 16; k++) w[k] = W2[j * 32 + half * 16 + k];

    const float4 b4  = reinterpret_cast<const float4*>(bias)[lane];
    const float4 g4  = reinterpret_cast<const float4*>(gamma)[lane];
    const float4 be4 = reinterpret_cast<const float4*>(beta)[lane];

    float* ysH = half ? &ys1[0][0] : &ys0[0][0];

    const int numTiles = (N + NPB - 1) / NPB;
    for (;;) {
        if (t == 0) s_tile = atomicAdd(&g_tile_ctr, 1);
        __syncthreads();
        const int tile = s_tile;
        if (tile >= numTiles) break;

        const int base  = tile * NPB;
        int valid = N - base; if (valid > NPB) valid = NPB;

        // Stage tile into shared (256 threads, 4 float4 each)
        const float4* X4 = reinterpret_cast<const float4*>(g_agg) + (size_t)base * D4;
        for (int i = t; i < NPB * D4; i += 256) {
            int r = i >> 5;
            xs[r][i & 31] = (r < valid) ? X4[i] : make_float4(0.f, 0.f, 0.f, 0.f);
        }
        __syncthreads();

        // Compute partial dot (K=64) for every node; no syncs inside
        for (int n = 0; n < NPB; n++) {
            unsigned long long a01a = 0ull, a23a = 0ull, a01b = 0ull, a23b = 0ull;
            const ulonglong2* xrow =
                reinterpret_cast<const ulonglong2*>(xs[n]) + half * 16;
#pragma unroll
            for (int k = 0; k < 16; k += 2) {
                ulonglong2 x0 = xrow[k];
                ulonglong2 x1 = xrow[k + 1];
                asm("fma.rn.f32x2 %0, %1, %2, %0;" : "+l"(a01a) : "l"(x0.x), "l"(w[k].x));
                asm("fma.rn.f32x2 %0, %1, %2, %0;" : "+l"(a23a) : "l"(x0.y), "l"(w[k].y));
                asm("fma.rn.f32x2 %0, %1, %2, %0;" : "+l"(a01b) : "l"(x1.x), "l"(w[k + 1].x));
                asm("fma.rn.f32x2 %0, %1, %2, %0;" : "+l"(a23b) : "l"(x1.y), "l"(w[k + 1].y));
            }
            // Packed reduction: combine chains with add.f32x2, then unpack once
            unsigned long long a01, a23;
            asm("add.rn.f32x2 %0, %1, %2;" : "=l"(a01) : "l"(a01a), "l"(a01b));
            asm("add.rn.f32x2 %0, %1, %2;" : "=l"(a23) : "l"(a23a), "l"(a23b));
            unsigned int l0, h0, l1, h1;
            asm("mov.b64 {%0, %1}, %2;" : "=r"(l0), "=r"(h0) : "l"(a01));
            asm("mov.b64 {%0, %1}, %2;" : "=r"(l1), "=r"(h1) : "l"(a23));
            float y = (__uint_as_float(l0) + __uint_as_float(h0)) +
                      (__uint_as_float(l1) + __uint_as_float(h1));
            ysH[n * D + j] = y;
        }
        __syncthreads();

        // Batched LN + ReLU: 8 warps, warp handles nodes warp, warp+8, ...
        // Combine split-K partials + bias fused into the loads.
        for (int n = warp; n < valid; n += 8) {
            float4 v0 = reinterpret_cast<const float4*>(ys0[n])[lane];
            float4 v1 = reinterpret_cast<const float4*>(ys1[n])[lane];
            float4 v;
            v.x = v0.x + v1.x + b4.x;
            v.y = v0.y + v1.y + b4.y;
            v.z = v0.z + v1.z + b4.z;
            v.w = v0.w + v1.w + b4.w;
            float s = (v.x + v.y) + (v.z + v.w);
            float q = (v.x * v.x + v.y * v.y) + (v.z * v.z + v.w * v.w);
#pragma unroll
            for (int o = 16; o > 0; o >>= 1) {
                s += __shfl_xor_sync(0xFFFFFFFFu, s, o);
                q += __shfl_xor_sync(0xFFFFFFFFu, q, o);
            }
            float mu  = s * (1.0f / D);
            float var = q * (1.0f / D) - mu * mu;
            float rs  = rsqrtf(var + LN_EPS);
            float4 o4;
            o4.x = fmaxf((v.x - mu) * rs * g4.x + be4.x, 0.f);
            o4.y = fmaxf((v.y - mu) * rs * g4.y + be4.y, 0.f);
            o4.z = fmaxf((v.z - mu) * rs * g4.z + be4.z, 0.f);
            o4.w = fmaxf((v.w - mu) * rs * g4.w + be4.w, 0.f);
            reinterpret_cast<float4*>(out + (size_t)(base + n) * D)[lane] = o4;
        }
        __syncthreads();   // xs/ys reused next tile
    }
}

// ---------------------------------------------------------------------------
extern "C" void kernel_launch(void* const* d_in, const int* in_sizes, int n_in,
                              void* d_out, int out_size) {
    const float* h     = (const float*)d_in[0];
    const int*   ei    = (const int*)d_in[1];   // [2, E] int32
    const float* W     = (const float*)d_in[2];
    const float* bias  = (const float*)d_in[3];
    const float* gamma = (const float*)d_in[4];
    const float* beta  = (const float*)d_in[5];
    float*       out   = (float*)d_out;

    const int N = in_sizes[0] / D;
    const int E = in_sizes[1] / 2;
    const int* src = ei;
    const int* dst = ei + E;

    // 1) agg = h  (+ tile-counter reset)
    int n4 = N * D4;
    k_init_agg<<<(n4 + 255) / 256, 256>>>(reinterpret_cast<const float4*>(h), n4);

    // 2) vectorized scatter-add: 1 warp per edge, 8 edges per 256-thread block
    int blocks_sc = (E + 7) / 8;
    k_scatter_v4<<<blocks_sc, 256>>>(reinterpret_cast<const float4*>(h), src, dst, E);

    // 3) fused linear (split-K) + layernorm + relu, dynamic tile scheduling
    k_gemm_ln_relu<<<GEMM_BLOCKS, 256>>>(W, bias, gamma, beta, out, N);
}

// round 16
// speedup vs baseline: 1.1706x; 1.1706x over previous
#include <cuda_runtime.h>
#include <cuda_bf16.h>
#include <cstdint>

#define D 128
#define D4 32
#define N_MAX 50000
#define LN_EPS 1e-5f
#define TILE_M 128
#define GEMM_CTAS 148

// ---------------- device globals ----------------
__device__ float g_agg[(size_t)N_MAX * D];
__device__ int   g_tile_ctr;
__device__ __nv_bfloat16 g_whi[128 * 128];   // W hi, swizzled image
__device__ __nv_bfloat16 g_wlo[128 * 128];   // W lo, swizzled image

// smem offsets (from 1024-aligned dynamic base)
#define OFF_A_HI   0          // 32 KB   (128 rows x 256B)
#define OFF_A_LO   32768
#define OFF_B_HI   65536
#define OFF_B_LO   98304
#define OFF_BIAS   131072     // 512B
#define OFF_GAMMA  131584
#define OFF_BETA   132096
#define OFF_TILE   132608
#define SMEM_TOTAL (132624 + 1040)

// Swizzled byte offset of 16B chunk c (0..15) in row `row` (256B rows).
// XOR of chunk index with (row&7) -> conflict-free ldmatrix & stores.
__host__ __device__ __forceinline__ uint32_t swz16(int row, int c) {
    return (uint32_t)(row * 256 + ((c ^ (row & 7)) << 4));
}

__device__ __forceinline__ uint32_t smem_u32(const void* p) {
    uint32_t a;
    asm("{ .reg .u64 t; cvta.to.shared.u64 t, %1; cvt.u32.u64 %0, t; }" : "=r"(a) : "l"(p));
    return a;
}

// ---------------------------------------------------------------------------
// Kernel 1: agg = h  (+ tile counter reset)
// ---------------------------------------------------------------------------
__global__ void k_init_agg(const float4* __restrict__ h4, int n4) {
    int i = blockIdx.x * blockDim.x + threadIdx.x;
    if (i == 0) g_tile_ctr = 0;
    float4* agg4 = reinterpret_cast<float4*>(g_agg);
    if (i < n4) agg4[i] = h4[i];
}

// ---------------------------------------------------------------------------
// Kernel 2: W -> hi/lo bf16 swizzled global images
// ---------------------------------------------------------------------------
__global__ void k_prep_w(const float* __restrict__ W) {
    int t = blockIdx.x * blockDim.x + threadIdx.x;
    for (int idx = t; idx < 128 * 128; idx += blockDim.x * gridDim.x) {
        int n = idx >> 7, k = idx & 127;
        float w = W[idx];
        __nv_bfloat16 hi = __float2bfloat16_rn(w);
        __nv_bfloat16 lo = __float2bfloat16_rn(w - __bfloat162float(hi));
        uint32_t o = (swz16(n, k >> 3) + ((k & 7) << 1)) >> 1;
        g_whi[o] = hi;
        g_wlo[o] = lo;
    }
}

// ---------------------------------------------------------------------------
// Kernel 3: vectorized scatter (at LTS atomic floor)
// ---------------------------------------------------------------------------
__global__ __launch_bounds__(256)
void k_scatter_v4(const float4* __restrict__ h4,
                  const int* __restrict__ src,
                  const int* __restrict__ dst,
                  int E) {
    int warp_id = (blockIdx.x * blockDim.x + threadIdx.x) >> 5;
    int lane = threadIdx.x & 31;
    if (warp_id >= E) return;
    int s = __ldg(src + warp_id);
    int d = __ldg(dst + warp_id);
    float4 v = h4[(size_t)s * D4 + lane];
    float4* ap = reinterpret_cast<float4*>(g_agg) + (size_t)d * D4 + lane;
    asm volatile("red.global.add.v4.f32 [%0], {%1, %2, %3, %4};"
                 :: "l"(ap), "f"(v.x), "f"(v.y), "f"(v.z), "f"(v.w) : "memory");
}

// ---------------------------------------------------------------------------
// Kernel 4: HMMA GEMM (hi/lo bf16, 3 passes) + bias + LayerNorm + ReLU
// 256 threads, 1 CTA/SM, persistent w/ dynamic tiles. Warp w owns rows
// [w*16, w*16+16) x all 128 cols: 16 m16n8 accum tiles in regs.
// ---------------------------------------------------------------------------
extern __shared__ char dsmem[];
__global__ __launch_bounds__(256, 1)
void k_mma_gemm(const float* __restrict__ bias,
                const float* __restrict__ gamma,
                const float* __restrict__ beta,
                float* __restrict__ out,
                int N) {
    uint32_t raw = smem_u32(dsmem);
    char* base = dsmem + ((1024 - (raw & 1023)) & 1023);
    const uint32_t sb = smem_u32(base);

    const int t = threadIdx.x;
    const int wid = t >> 5;
    const int lane = t & 31;

    // one-time: W images + vectors into smem
    {
        const uint4* whi4 = reinterpret_cast<const uint4*>(g_whi);
        const uint4* wlo4 = reinterpret_cast<const uint4*>(g_wlo);
        uint4* bhi4 = reinterpret_cast<uint4*>(base + OFF_B_HI);
        uint4* blo4 = reinterpret_cast<uint4*>(base + OFF_B_LO);
        for (int i = t; i < 2048; i += 256) { bhi4[i] = whi4[i]; blo4[i] = wlo4[i]; }
        float* sbi = reinterpret_cast<float*>(base + OFF_BIAS);
        float* sga = reinterpret_cast<float*>(base + OFF_GAMMA);
        float* sbe = reinterpret_cast<float*>(base + OFF_BETA);
        if (t < 128) { sbi[t] = bias[t]; sga[t] = gamma[t]; sbe[t] = beta[t]; }
    }

    int* s_tl = reinterpret_cast<int*>(base + OFF_TILE);
    const float* sbi = reinterpret_cast<const float*>(base + OFF_BIAS);
    const float* sga = reinterpret_cast<const float*>(base + OFF_GAMMA);
    const float* sbe = reinterpret_cast<const float*>(base + OFF_BETA);

    // per-lane constants for fragment addressing
    const int l7   = lane & 7;
    const int bsel = (lane >> 3) & 1;                  // B: k-chunk select
    const int arow = wid * 16 + (bsel << 3) + l7;      // A: row for this lane
    const uint32_t arow_off = (uint32_t)arow * 256;
    const int a_r7 = arow & 7;
    const int aksel = lane >> 4;                       // A: k-chunk select
    const uint32_t brow_off = (uint32_t)l7 * 256;
    const int qlane = lane & 3;
    const int mrowA = wid * 16 + (lane >> 2);          // accum row A (row B = +8)

    const int numTiles = (N + TILE_M - 1) / TILE_M;

    for (;;) {
        if (t == 0) *s_tl = atomicAdd(&g_tile_ctr, 1);
        __syncthreads();                                // also fences prev tile's smem use
        const int tile = *s_tl;
        if (tile >= numTiles) break;
        const int base_row = tile * TILE_M;

        // ---- stage A: x -> bf16 hi/lo, swizzled. thread: row t>>1, k-half t&1 ----
        {
            const int row = t >> 1;
            const int kh = t & 1;
            int gr = base_row + row; if (gr >= N) gr = N - 1;
            const float4* xr = reinterpret_cast<const float4*>(g_agg + (size_t)gr * 128) + kh * 16;
            char* Ah = base + OFF_A_HI;
            char* Al = base + OFF_A_LO;
#pragma unroll
            for (int i = 0; i < 8; i++) {
                float4 u = xr[i * 2];
                float4 v = xr[i * 2 + 1];
                float f[8] = {u.x, u.y, u.z, u.w, v.x, v.y, v.z, v.w};
                unsigned short hs[8], ls[8];
#pragma unroll
                for (int e = 0; e < 8; e++) {
                    __nv_bfloat16 hb = __float2bfloat16_rn(f[e]);
                    float r = f[e] - __bfloat162float(hb);
                    __nv_bfloat16 lb = __float2bfloat16_rn(r);
                    hs[e] = __bfloat16_as_ushort(hb);
                    ls[e] = __bfloat16_as_ushort(lb);
                }
                uint4 hp = make_uint4((uint32_t)hs[0] | ((uint32_t)hs[1] << 16),
                                      (uint32_t)hs[2] | ((uint32_t)hs[3] << 16),
                                      (uint32_t)hs[4] | ((uint32_t)hs[5] << 16),
                                      (uint32_t)hs[6] | ((uint32_t)hs[7] << 16));
                uint4 lp = make_uint4((uint32_t)ls[0] | ((uint32_t)ls[1] << 16),
                                      (uint32_t)ls[2] | ((uint32_t)ls[3] << 16),
                                      (uint32_t)ls[4] | ((uint32_t)ls[5] << 16),
                                      (uint32_t)ls[6] | ((uint32_t)ls[7] << 16));
                uint32_t off = swz16(row, kh * 8 + i);
                *reinterpret_cast<uint4*>(Ah + off) = hp;
                *reinterpret_cast<uint4*>(Al + off) = lp;
            }
        }
        __syncthreads();

        // ---- 3-pass MMA: D = Ah*Bh + Ah*Bl + Al*Bh ----
        float acc[16][4];
#pragma unroll
        for (int nt = 0; nt < 16; nt++)
            acc[nt][0] = acc[nt][1] = acc[nt][2] = acc[nt][3] = 0.f;

#pragma unroll
        for (int pass = 0; pass < 3; pass++) {
            const uint32_t SA = sb + ((pass == 2) ? OFF_A_LO : OFF_A_HI);
            const uint32_t SB = sb + ((pass == 1) ? OFF_B_LO : OFF_B_HI);
#pragma unroll
            for (int ks = 0; ks < 8; ks++) {
                uint32_t a0, a1, a2, a3;
                {
                    int ac = ks * 2 + aksel;
                    uint32_t aaddr = SA + arow_off + (uint32_t)((ac ^ a_r7) << 4);
                    asm volatile("ldmatrix.sync.aligned.m8n8.x4.shared.b16 {%0,%1,%2,%3}, [%4];"
                                 : "=r"(a0), "=r"(a1), "=r"(a2), "=r"(a3) : "r"(aaddr));
                }
                const int bc = ks * 2 + bsel;
                const uint32_t bx = (uint32_t)((bc ^ l7) << 4);
#pragma unroll
                for (int nt = 0; nt < 16; nt++) {
                    uint32_t b0, b1;
                    uint32_t baddr = SB + brow_off + (uint32_t)(nt * 2048) + bx;
                    asm volatile("ldmatrix.sync.aligned.m8n8.x2.shared.b16 {%0,%1}, [%2];"
                                 : "=r"(b0), "=r"(b1) : "r"(baddr));
                    asm volatile("mma.sync.aligned.m16n8k16.row.col.f32.bf16.bf16.f32 "
                                 "{%0,%1,%2,%3}, {%4,%5,%6,%7}, {%8,%9}, {%0,%1,%2,%3};"
                                 : "+f"(acc[nt][0]), "+f"(acc[nt][1]),
                                   "+f"(acc[nt][2]), "+f"(acc[nt][3])
                                 : "r"(a0), "r"(a1), "r"(a2), "r"(a3), "r"(b0), "r"(b1));
                }
            }
        }

        // ---- bias + LN + ReLU from register accumulators ----
        float sA = 0.f, qA = 0.f, sB = 0.f, qB = 0.f;
#pragma unroll
        for (int nt = 0; nt < 16; nt++) {
            int col = nt * 8 + qlane * 2;
            float b0 = sbi[col], b1 = sbi[col + 1];
            acc[nt][0] += b0; acc[nt][1] += b1;
            acc[nt][2] += b0; acc[nt][3] += b1;
            sA += acc[nt][0] + acc[nt][1];
            qA += acc[nt][0] * acc[nt][0] + acc[nt][1] * acc[nt][1];
            sB += acc[nt][2] + acc[nt][3];
            qB += acc[nt][2] * acc[nt][2] + acc[nt][3] * acc[nt][3];
        }
        sA += __shfl_xor_sync(0xFFFFFFFFu, sA, 1); sA += __shfl_xor_sync(0xFFFFFFFFu, sA, 2);
        qA += __shfl_xor_sync(0xFFFFFFFFu, qA, 1); qA += __shfl_xor_sync(0xFFFFFFFFu, qA, 2);
        sB += __shfl_xor_sync(0xFFFFFFFFu, sB, 1); sB += __shfl_xor_sync(0xFFFFFFFFu, sB, 2);
        qB += __shfl_xor_sync(0xFFFFFFFFu, qB, 1); qB += __shfl_xor_sync(0xFFFFFFFFu, qB, 2);

        float muA = sA * (1.0f / 128.0f);
        float rsA = rsqrtf(qA * (1.0f / 128.0f) - muA * muA + LN_EPS);
        float muB = sB * (1.0f / 128.0f);
        float rsB = rsqrtf(qB * (1.0f / 128.0f) - muB * muB + LN_EPS);

        const int gA = base_row + mrowA;
        const int gB = gA + 8;
#pragma unroll
        for (int nt = 0; nt < 16; nt++) {
            int col = nt * 8 + qlane * 2;
            float g0 = sga[col], g1 = sga[col + 1];
            float e0 = sbe[col], e1 = sbe[col + 1];
            if (gA < N) {
                float2 o;
                o.x = fmaxf((acc[nt][0] - muA) * rsA * g0 + e0, 0.f);
                o.y = fmaxf((acc[nt][1] - muA) * rsA * g1 + e1, 0.f);
                *reinterpret_cast<float2*>(out + (size_t)gA * 128 + col) = o;
            }
            if (gB < N) {
                float2 o;
                o.x = fmaxf((acc[nt][2] - muB) * rsB * g0 + e0, 0.f);
                o.y = fmaxf((acc[nt][3] - muB) * rsB * g1 + e1, 0.f);
                *reinterpret_cast<float2*>(out + (size_t)gB * 128 + col) = o;
            }
        }
    }
}

// ---------------------------------------------------------------------------
extern "C" void kernel_launch(void* const* d_in, const int* in_sizes, int n_in,
                              void* d_out, int out_size) {
    const float* h     = (const float*)d_in[0];
    const int*   ei    = (const int*)d_in[1];
    const float* W     = (const float*)d_in[2];
    const float* bias  = (const float*)d_in[3];
    const float* gamma = (const float*)d_in[4];
    const float* beta  = (const float*)d_in[5];
    float*       out   = (float*)d_out;

    const int N = in_sizes[0] / D;
    const int E = in_sizes[1] / 2;
    const int* src = ei;
    const int* dst = ei + E;

    static bool attr_set = false;
    if (!attr_set) {
        cudaFuncSetAttribute(k_mma_gemm, cudaFuncAttributeMaxDynamicSharedMemorySize, SMEM_TOTAL);
        attr_set = true;
    }

    int n4 = N * D4;
    k_init_agg<<<(n4 + 255) / 256, 256>>>(reinterpret_cast<const float4*>(h), n4);
    k_prep_w<<<64, 256>>>(W);
    k_scatter_v4<<<(E + 7) / 8, 256>>>(reinterpret_cast<const float4*>(h), src, dst, E);
    k_mma_gemm<<<GEMM_CTAS, 256, SMEM_TOTAL>>>(bias, gamma, beta, out, N);
}